// round 1
// baseline (speedup 1.0000x reference)
#include <cuda_runtime.h>
#include <cstdint>

#define N_LAYERS 512
#define BATCH    131072
#define NPAIR    (BATCH / 2)

__device__ __forceinline__ unsigned long long pack2(float a, float b) {
    unsigned long long r;
    asm("mov.b64 %0, {%1, %2};" : "=l"(r) : "f"(a), "f"(b));
    return r;
}
__device__ __forceinline__ unsigned long long bcast2(float a) { return pack2(a, a); }
__device__ __forceinline__ void unpack2(unsigned long long v, float& a, float& b) {
    asm("mov.b64 {%0, %1}, %2;" : "=f"(a), "=f"(b) : "l"(v));
}

#define FMA2(d, a, b, c) asm("fma.rn.f32x2 %0, %1, %2, %3;" : "=l"(d) : "l"(a), "l"(b), "l"(c))
#define MUL2(d, a, b)    asm("mul.rn.f32x2 %0, %1, %2;"     : "=l"(d) : "l"(a), "l"(b))
#define ADD2(d, a, b)    asm("add.rn.f32x2 %0, %1, %2;"     : "=l"(d) : "l"(a), "l"(b))

__global__ __launch_bounds__(256, 2)
void metricnet_kernel(const float* __restrict__ Re_s,
                      const float* __restrict__ Im_s,
                      const float* __restrict__ Omega,
                      const float* __restrict__ PiT,
                      const float* __restrict__ B,
                      float* __restrict__ out)
{
    const float DEL_Z = 0.9f / 512.0f;
    const float MU2   = 1.0f;

    // Per-layer packed coefficient tables (layer-uniform, broadcast reads).
    __shared__ ulonglong2          tabPQ[N_LAYERS];  // {P, Q}
    __shared__ ulonglong2          tabCR[N_LAYERS];  // {inv1, R}
    __shared__ unsigned long long  tabU [N_LAYERS];  // U

    const int tid = threadIdx.x;
    const float pit = PiT[0];

    for (int l = tid; l < N_LAYERS; l += blockDim.x) {
        float z    = DEL_Z * (float)l;          // Z_INI = 0
        float omz  = 1.0f - z;
        float inv1 = 1.0f / (pit * omz);
        float inv2 = inv1 / omz;
        float b1   = B[l];
        float b2   = B[l + 1];
        float g    = 1.0f - b2 / b1;
        float P    = 1.0f + g;
        float Q    = g * inv1 - DEL_Z * inv2;
        float R    = DEL_Z * (1.0f / (b1 * b1) - inv2 / pit);
        float U    = DEL_Z * z * z * MU2 / b1;
        tabPQ[l] = make_ulonglong2(bcast2(P), bcast2(Q));
        tabCR[l] = make_ulonglong2(bcast2(inv1), bcast2(R));
        tabU[l]  = bcast2(U);
    }
    __syncthreads();

    const int i = blockIdx.x * blockDim.x + tid;   // pair index
    if (i >= NPAIR) return;

    const float2 re0 = ((const float2*)Re_s)[i];
    const float2 im0 = ((const float2*)Im_s)[i];
    const float2 om  = ((const float2*)Omega)[i];

    // Per-thread packed constants derived from omega (two lanes).
    unsigned long long Re  = pack2(re0.x, re0.y);
    unsigned long long Im  = pack2(im0.x, im0.y);
    unsigned long long W   = pack2(om.x, om.y);
    unsigned long long TW  = pack2( 2.0f * DEL_Z * om.x,  2.0f * DEL_Z * om.y);
    unsigned long long NTW = pack2(-2.0f * DEL_Z * om.x, -2.0f * DEL_Z * om.y);
    unsigned long long DW  = pack2( DEL_Z * om.x,  DEL_Z * om.y);
    unsigned long long NDW = pack2(-DEL_Z * om.x, -DEL_Z * om.y);
    unsigned long long NIW = pack2(-1.0f / om.x, -1.0f / om.y);

    #pragma unroll 4
    for (int l = 0; l < N_LAYERS; ++l) {
        ulonglong2 c0 = tabPQ[l];
        ulonglong2 c1 = tabCR[l];
        unsigned long long U = tabU[l];
        unsigned long long P = c0.x, Q = c0.y, C1 = c1.x, R = c1.y;

        unsigned long long t0, t1, wr, rr, ii, cr, Ren, Imn;
        // Re_n = P*Re + Q + TW*Im*(Re + C1)
        ADD2(t0, Re, C1);
        MUL2(t1, Im, t0);
        FMA2(Ren, P, Re, Q);
        FMA2(Ren, TW, t1, Ren);
        // Im_n = P*Im + W*R + DW*Im^2 - DW*Re_n^2 - TW*(C1*Re_n) + U*(-1/W)
        MUL2(wr, W, R);
        FMA2(Imn, P, Im, wr);
        MUL2(rr, Ren, Ren);
        FMA2(Imn, NDW, rr, Imn);
        MUL2(ii, Im, Im);
        FMA2(Imn, DW, ii, Imn);
        MUL2(cr, C1, Ren);
        FMA2(Imn, NTW, cr, Imn);
        FMA2(Imn, U, NIW, Imn);

        Re = Ren;
        Im = Imn;
    }

    float2 reo, imo;
    unpack2(Re, reo.x, reo.y);
    unpack2(Im, imo.x, imo.y);
    ((float2*)out)[i]                   = reo;   // Re_f  -> out[0 : BATCH)
    ((float2*)(out + BATCH))[i]         = imo;   // Im_f  -> out[BATCH : 2*BATCH)
}

extern "C" void kernel_launch(void* const* d_in, const int* in_sizes, int n_in,
                              void* d_out, int out_size)
{
    const float* Re_s  = (const float*)d_in[0];
    const float* Im_s  = (const float*)d_in[1];
    const float* Omega = (const float*)d_in[2];
    const float* PiT   = (const float*)d_in[3];
    const float* B     = (const float*)d_in[4];
    float* out = (float*)d_out;

    const int threads = 256;
    const int blocks  = (NPAIR + threads - 1) / threads;   // 256 blocks
    metricnet_kernel<<<blocks, threads>>>(Re_s, Im_s, Omega, PiT, B, out);
}

// round 3
// speedup vs baseline: 1.0999x; 1.0999x over previous
#include <cuda_runtime.h>
#include <cstdint>

#define N_LAYERS 512
#define BATCH    131072
#define NPAIR    (BATCH / 2)

typedef unsigned long long u64;

__device__ __forceinline__ u64 pack2(float a, float b) {
    u64 r;
    asm("mov.b64 %0, {%1, %2};" : "=l"(r) : "f"(a), "f"(b));
    return r;
}
__device__ __forceinline__ u64 bcast2(float a) { return pack2(a, a); }
__device__ __forceinline__ void unpack2(u64 v, float& a, float& b) {
    asm("mov.b64 {%0, %1}, %2;" : "=f"(a), "=f"(b) : "l"(v));
}

#define FMA2(d, a, b, c) asm("fma.rn.f32x2 %0, %1, %2, %3;" : "=l"(d) : "l"(a), "l"(b), "l"(c))
#define MUL2(d, a, b)    asm("mul.rn.f32x2 %0, %1, %2;"     : "=l"(d) : "l"(a), "l"(b))
#define ADD2(d, a, b)    asm("add.rn.f32x2 %0, %1, %2;"     : "=l"(d) : "l"(a), "l"(b))

__global__ __launch_bounds__(256, 2)
void metricnet_kernel(const float* __restrict__ Re_s,
                      const float* __restrict__ Im_s,
                      const float* __restrict__ Omega,
                      const float* __restrict__ PiT,
                      const float* __restrict__ B,
                      float* __restrict__ out)
{
    const float DEL_Z = 0.9f / 512.0f;
    const float MU2   = 1.0f;

    // Per-layer packed (duplicated-lane) coefficient tables; broadcast LDS reads.
    __shared__ ulonglong2 tabPQ[N_LAYERS];  // {P, Q}
    __shared__ ulonglong2 tabCR[N_LAYERS];  // {C1(=inv1), R}
    __shared__ u64        tabU [N_LAYERS];  // U

    const int tid = threadIdx.x;
    const float pit = PiT[0];

    for (int l = tid; l < N_LAYERS; l += blockDim.x) {
        float z    = DEL_Z * (float)l;          // Z_INI = 0
        float omz  = 1.0f - z;
        float inv1 = 1.0f / (pit * omz);
        float inv2 = inv1 / omz;
        float b1   = B[l];
        float b2   = B[l + 1];
        float g    = 1.0f - b2 / b1;
        float P    = 1.0f + g;
        float Q    = g * inv1 - DEL_Z * inv2;
        float R    = DEL_Z * (1.0f / (b1 * b1) - inv2 / pit);
        float U    = DEL_Z * z * z * MU2 / b1;
        tabPQ[l] = make_ulonglong2(bcast2(P), bcast2(Q));
        tabCR[l] = make_ulonglong2(bcast2(inv1), bcast2(R));
        tabU[l]  = bcast2(U);
    }
    __syncthreads();

    const int i = blockIdx.x * blockDim.x + tid;   // pair index
    if (i >= NPAIR) return;

    const float2 re0 = ((const float2*)Re_s)[i];
    const float2 im0 = ((const float2*)Im_s)[i];
    const float2 om  = ((const float2*)Omega)[i];

    // Per-thread packed constants derived from omega (two independent lanes).
    u64 Re  = pack2(re0.x, re0.y);
    u64 Im  = pack2(im0.x, im0.y);
    u64 W   = pack2(om.x, om.y);
    u64 TW  = pack2( 2.0f * DEL_Z * om.x,  2.0f * DEL_Z * om.y);
    u64 NTW = pack2(-2.0f * DEL_Z * om.x, -2.0f * DEL_Z * om.y);
    u64 DW  = pack2( DEL_Z * om.x,  DEL_Z * om.y);
    u64 NDW = pack2(-DEL_Z * om.x, -DEL_Z * om.y);
    u64 NIW = pack2(-1.0f / om.x, -1.0f / om.y);

    #pragma unroll 8
    for (int l = 0; l < N_LAYERS; ++l) {
        ulonglong2 c0 = tabPQ[l];       // P, Q
        ulonglong2 c1 = tabCR[l];       // C1, R
        u64 U  = tabU[l];
        u64 P  = c0.x, Q = c0.y, C1 = c1.x, R = c1.y;

        // ---- off-critical-path (no Re/Im dependence) ----
        u64 wr2, tc;
        MUL2(wr2, W, R);                // W*R
        FMA2(wr2, U, NIW, wr2);         // W*R - U/W
        MUL2(tc, NTW, C1);              // -TW*C1

        // ---- Re_n = P*Re + Q + (TW*Im)*(Re + C1)   (chain: +8) ----
        u64 t0, h, Ren;
        ADD2(t0, Re, C1);
        MUL2(h, TW, Im);
        FMA2(Ren, P, Re, Q);
        FMA2(Ren, h, t0, Ren);

        // ---- Im_n = Im*(P + DW*Im) + wr2 + Ren*(NDW*Ren + tc)  (chain: +16) ----
        u64 m, pA, v, Imn;
        FMA2(m, DW, Im, P);             // P + DW*Im
        FMA2(pA, Im, m, wr2);           // P*Im + DW*Im^2 + W*R - U/W
        FMA2(v, NDW, Ren, tc);          // -DW*Ren - TW*C1
        FMA2(Imn, Ren, v, pA);          // += -DW*Ren^2 - TW*C1*Ren

        Re = Ren;
        Im = Imn;
    }

    float2 reo, imo;
    unpack2(Re, reo.x, reo.y);
    unpack2(Im, imo.x, imo.y);
    ((float2*)out)[i]           = reo;   // Re_f -> out[0 : BATCH)
    ((float2*)(out + BATCH))[i] = imo;   // Im_f -> out[BATCH : 2*BATCH)
}

extern "C" void kernel_launch(void* const* d_in, const int* in_sizes, int n_in,
                              void* d_out, int out_size)
{
    const float* Re_s  = (const float*)d_in[0];
    const float* Im_s  = (const float*)d_in[1];
    const float* Omega = (const float*)d_in[2];
    const float* PiT   = (const float*)d_in[3];
    const float* B     = (const float*)d_in[4];
    float* out = (float*)d_out;

    const int threads = 256;
    const int blocks  = (NPAIR + threads - 1) / threads;   // 256 blocks
    metricnet_kernel<<<blocks, threads>>>(Re_s, Im_s, Omega, PiT, B, out);
}

// round 4
// speedup vs baseline: 1.1008x; 1.0008x over previous
#include <cuda_runtime.h>
#include <cstdint>

#define N_LAYERS 512
#define BATCH    131072
#define NPAIR    (BATCH / 2)
#define TAB_N    (N_LAYERS + 1)      // padded for branch-free prefetch

typedef unsigned long long u64;

__device__ __forceinline__ u64 pack2(float a, float b) {
    u64 r;
    asm("mov.b64 %0, {%1, %2};" : "=l"(r) : "f"(a), "f"(b));
    return r;
}
__device__ __forceinline__ u64 bcast2(float a) { return pack2(a, a); }
__device__ __forceinline__ void unpack2(u64 v, float& a, float& b) {
    asm("mov.b64 {%0, %1}, %2;" : "=f"(a), "=f"(b) : "l"(v));
}

#define FMA2(d, a, b, c) asm("fma.rn.f32x2 %0, %1, %2, %3;" : "=l"(d) : "l"(a), "l"(b), "l"(c))
#define MUL2(d, a, b)    asm("mul.rn.f32x2 %0, %1, %2;"     : "=l"(d) : "l"(a), "l"(b))
#define ADD2(d, a, b)    asm("add.rn.f32x2 %0, %1, %2;"     : "=l"(d) : "l"(a), "l"(b))

__global__ __launch_bounds__(128, 4)
void metricnet_kernel(const float* __restrict__ Re_s,
                      const float* __restrict__ Im_s,
                      const float* __restrict__ Omega,
                      const float* __restrict__ PiT,
                      const float* __restrict__ B,
                      float* __restrict__ out)
{
    const float DEL_Z = 0.9f / 512.0f;
    const float MU2   = 1.0f;

    // Per-layer packed (duplicated-lane) coefficient tables; broadcast LDS reads.
    __shared__ ulonglong2 tabPQ[TAB_N];  // {P, Q}
    __shared__ ulonglong2 tabCR[TAB_N];  // {C1(=inv1), R}
    __shared__ u64        tabU [TAB_N];  // U

    const int tid = threadIdx.x;
    const float pit = PiT[0];

    for (int l = tid; l < TAB_N; l += blockDim.x) {
        int  lc   = (l < N_LAYERS) ? l : (N_LAYERS - 1);   // pad entry = copy
        float z    = DEL_Z * (float)lc;          // Z_INI = 0
        float omz  = 1.0f - z;
        float inv1 = 1.0f / (pit * omz);
        float inv2 = inv1 / omz;
        float b1   = B[lc];
        float b2   = B[lc + 1];
        float g    = 1.0f - b2 / b1;
        float P    = 1.0f + g;
        float Q    = g * inv1 - DEL_Z * inv2;
        float R    = DEL_Z * (1.0f / (b1 * b1) - inv2 / pit);
        float U    = DEL_Z * z * z * MU2 / b1;
        tabPQ[l] = make_ulonglong2(bcast2(P), bcast2(Q));
        tabCR[l] = make_ulonglong2(bcast2(inv1), bcast2(R));
        tabU[l]  = bcast2(U);
    }
    __syncthreads();

    const int i = blockIdx.x * blockDim.x + tid;   // pair index
    if (i >= NPAIR) return;

    const float2 re0 = ((const float2*)Re_s)[i];
    const float2 im0 = ((const float2*)Im_s)[i];
    const float2 om  = ((const float2*)Omega)[i];

    // Per-thread packed constants derived from omega (two independent lanes).
    u64 Re  = pack2(re0.x, re0.y);
    u64 Im  = pack2(im0.x, im0.y);
    u64 W   = pack2(om.x, om.y);
    u64 TW  = pack2( 2.0f * DEL_Z * om.x,  2.0f * DEL_Z * om.y);
    u64 NTW = pack2(-2.0f * DEL_Z * om.x, -2.0f * DEL_Z * om.y);
    u64 DW  = pack2( DEL_Z * om.x,  DEL_Z * om.y);
    u64 NDW = pack2(-DEL_Z * om.x, -DEL_Z * om.y);
    u64 NIW = pack2(-1.0f / om.x, -1.0f / om.y);

    // ---- software prefetch-by-1 through named registers ----
    ulonglong2 c0 = tabPQ[0];           // P, Q
    ulonglong2 c1 = tabCR[0];           // C1, R
    u64        cu = tabU[0];            // U

    #pragma unroll 4
    for (int l = 0; l < N_LAYERS; ++l) {
        // Issue next iteration's loads FIRST (covered by this iter's FMA chain).
        ulonglong2 n0 = tabPQ[l + 1];
        ulonglong2 n1 = tabCR[l + 1];
        u64        nu = tabU[l + 1];

        u64 P = c0.x, Q = c0.y, C1 = c1.x, R = c1.y, U = cu;

        // ---- off-critical-path (no Re/Im dependence) ----
        u64 wr2, tc;
        MUL2(wr2, W, R);                // W*R
        FMA2(wr2, U, NIW, wr2);         // W*R - U/W
        MUL2(tc, NTW, C1);              // -TW*C1

        // ---- Re_n = P*Re + Q + (TW*Im)*(Re + C1) ----
        u64 t0, h, Ren;
        ADD2(t0, Re, C1);
        MUL2(h, TW, Im);
        FMA2(Ren, P, Re, Q);
        FMA2(Ren, h, t0, Ren);

        // ---- Im_n = Im*(P + DW*Im) + wr2 + Ren*(NDW*Ren + tc) ----
        u64 m, pA, v, Imn;
        FMA2(m, DW, Im, P);             // P + DW*Im
        FMA2(pA, Im, m, wr2);           // P*Im + DW*Im^2 + W*R - U/W
        FMA2(v, NDW, Ren, tc);          // -DW*Ren - TW*C1
        FMA2(Imn, Ren, v, pA);          // += -DW*Ren^2 - TW*C1*Ren

        Re = Ren;
        Im = Imn;

        c0 = n0; c1 = n1; cu = nu;
    }

    float2 reo, imo;
    unpack2(Re, reo.x, reo.y);
    unpack2(Im, imo.x, imo.y);
    ((float2*)out)[i]           = reo;   // Re_f -> out[0 : BATCH)
    ((float2*)(out + BATCH))[i] = imo;   // Im_f -> out[BATCH : 2*BATCH)
}

extern "C" void kernel_launch(void* const* d_in, const int* in_sizes, int n_in,
                              void* d_out, int out_size)
{
    const float* Re_s  = (const float*)d_in[0];
    const float* Im_s  = (const float*)d_in[1];
    const float* Omega = (const float*)d_in[2];
    const float* PiT   = (const float*)d_in[3];
    const float* B     = (const float*)d_in[4];
    float* out = (float*)d_out;

    const int threads = 128;
    const int blocks  = (NPAIR + threads - 1) / threads;   // 512 blocks
    metricnet_kernel<<<blocks, threads>>>(Re_s, Im_s, Omega, PiT, B, out);
}

// round 7
// speedup vs baseline: 1.2231x; 1.1111x over previous
#include <cuda_runtime.h>
#include <cstdint>

#define N_LAYERS 512
#define BATCH    131072
#define NPAIR    (BATCH / 2)
#define TAB_N    (N_LAYERS + 1)      // padded for branch-free prefetch

typedef unsigned long long u64;

__device__ __forceinline__ u64 pack2(float a, float b) {
    u64 r;
    asm("mov.b64 %0, {%1, %2};" : "=l"(r) : "f"(a), "f"(b));
    return r;
}
__device__ __forceinline__ u64 bcast2(float a) { return pack2(a, a); }
__device__ __forceinline__ void unpack2(u64 v, float& a, float& b) {
    asm("mov.b64 {%0, %1}, %2;" : "=f"(a), "=f"(b) : "l"(v));
}

#define FMA2(d, a, b, c) asm("fma.rn.f32x2 %0, %1, %2, %3;" : "=l"(d) : "l"(a), "l"(b), "l"(c))
#define MUL2(d, a, b)    asm("mul.rn.f32x2 %0, %1, %2;"     : "=l"(d) : "l"(a), "l"(b))
#define ADD2(d, a, b)    asm("add.rn.f32x2 %0, %1, %2;"     : "=l"(d) : "l"(a), "l"(b))

__global__ __launch_bounds__(128, 4)
void metricnet_kernel(const float* __restrict__ Re_s,
                      const float* __restrict__ Im_s,
                      const float* __restrict__ Omega,
                      const float* __restrict__ PiT,
                      const float* __restrict__ B,
                      float* __restrict__ out)
{
    const float DEL_Z = 0.9f / 512.0f;
    const float MU2   = 1.0f;

    // Per-layer packed (duplicated-lane) coefficient tables; broadcast LDS reads.
    // Record: {P, Q} {C1d(=2*inv1), Ra(=DEL_Z*R)} {Ua(=-DEL_Z*U)}
    __shared__ ulonglong2 tabPQ[TAB_N];
    __shared__ ulonglong2 tabCR[TAB_N];
    __shared__ u64        tabU [TAB_N];

    const int tid = threadIdx.x;
    const float pit = PiT[0];

    for (int l = tid; l < TAB_N; l += blockDim.x) {
        int   lc   = (l < N_LAYERS) ? l : (N_LAYERS - 1);   // pad entry = copy
        float z    = DEL_Z * (float)lc;          // Z_INI = 0
        float omz  = 1.0f - z;
        float inv1 = 1.0f / (pit * omz);
        float inv2 = inv1 / omz;
        float b1   = B[lc];
        float b2   = B[lc + 1];
        float g    = 1.0f - b2 / b1;
        float P    = 1.0f + g;
        float Q    = g * inv1 - DEL_Z * inv2;
        float R    = DEL_Z * (1.0f / (b1 * b1) - inv2 / pit);
        float U    = DEL_Z * z * z * MU2 / b1;
        // Scaled-state (m = DEL_Z*omega*Im) forcing constants:
        //   m_n += DEL_Z*omega*(omega*R - U/omega) = omega^2*(DEL_Z*R) - DEL_Z*U
        float Ra   = DEL_Z * R;
        float Ua   = -DEL_Z * U;
        tabPQ[l] = make_ulonglong2(bcast2(P), bcast2(Q));
        tabCR[l] = make_ulonglong2(bcast2(2.0f * inv1), bcast2(Ra));
        tabU[l]  = bcast2(Ua);
    }
    __syncthreads();

    const int i = blockIdx.x * blockDim.x + tid;   // pair index
    if (i >= NPAIR) return;

    const float2 re0 = ((const float2*)Re_s)[i];
    const float2 im0 = ((const float2*)Im_s)[i];
    const float2 om  = ((const float2*)Omega)[i];

    // Scaled state: m = (DEL_Z*omega) * Im.  Re stays unscaled.
    const float dwx = DEL_Z * om.x, dwy = DEL_Z * om.y;
    u64 Re  = pack2(re0.x, re0.y);
    u64 Mm  = pack2(dwx * im0.x, dwy * im0.y);
    u64 DW  = pack2( dwx,  dwy);
    u64 NDW = pack2(-dwx, -dwy);
    u64 W2  = pack2(om.x * om.x, om.y * om.y);
    u64 TWO = bcast2(2.0f);

    // software prefetch-by-1 through named registers
    ulonglong2 c0 = tabPQ[0];           // P, Q
    ulonglong2 c1 = tabCR[0];           // C1d, Ra
    u64        cu = tabU[0];            // Ua

    #pragma unroll 4
    for (int l = 0; l < N_LAYERS; ++l) {
        ulonglong2 n0 = tabPQ[l + 1];
        ulonglong2 n1 = tabCR[l + 1];
        u64        nu = tabU[l + 1];

        u64 P = c0.x, Q = c0.y, C1d = c1.x, Ra = c1.y, Ua = cu;

        // off-critical-path layer×thread combines
        u64 Cp, ntc;
        FMA2(Cp, W2, Ra, Ua);           // omega^2*DEL_Z*R - DEL_Z*U
        MUL2(ntc, NDW, C1d);            // -(DEL_Z*omega)*2*inv1

        // Re_n = P*Re + Q + m*(2*Re + C1d)
        u64 t0, r0, Ren;
        FMA2(t0, TWO, Re, C1d);
        FMA2(r0, P, Re, Q);
        FMA2(Ren, Mm, t0, r0);

        // m_n = m*(m + P) + Cp + q*(-q + ntc),  q = DW*Ren
        u64 s, acc, q, v, Mn;
        ADD2(s, Mm, P);
        FMA2(acc, Mm, s, Cp);
        MUL2(q, DW, Ren);
        FMA2(v, NDW, Ren, ntc);         // -q - (DEL_Z*omega)*C1d
        FMA2(Mn, q, v, acc);

        Re = Ren;
        Mm = Mn;

        c0 = n0; c1 = n1; cu = nu;
    }

    float2 reo, mo;
    unpack2(Re, reo.x, reo.y);
    unpack2(Mm, mo.x, mo.y);
    float2 imo;
    imo.x = mo.x / dwx;                 // Im = m / (DEL_Z*omega)
    imo.y = mo.y / dwy;
    ((float2*)out)[i]           = reo;   // Re_f -> out[0 : BATCH)
    ((float2*)(out + BATCH))[i] = imo;   // Im_f -> out[BATCH : 2*BATCH)
}

extern "C" void kernel_launch(void* const* d_in, const int* in_sizes, int n_in,
                              void* d_out, int out_size)
{
    const float* Re_s  = (const float*)d_in[0];
    const float* Im_s  = (const float*)d_in[1];
    const float* Omega = (const float*)d_in[2];
    const float* PiT   = (const float*)d_in[3];
    const float* B     = (const float*)d_in[4];
    float* out = (float*)d_out;

    const int threads = 128;
    const int blocks  = (NPAIR + threads - 1) / threads;   // 512 blocks
    metricnet_kernel<<<blocks, threads>>>(Re_s, Im_s, Omega, PiT, B, out);
}

// round 8
// speedup vs baseline: 1.3381x; 1.0940x over previous
#include <cuda_runtime.h>
#include <cstdint>

#define N_LAYERS 512
#define BATCH    131072
#define NPAIR    (BATCH / 2)
#define TAB_N    (N_LAYERS + 1)      // padded for branch-free prefetch

typedef unsigned long long u64;

__device__ __forceinline__ u64 pack2(float a, float b) {
    u64 r;
    asm("mov.b64 %0, {%1, %2};" : "=l"(r) : "f"(a), "f"(b));
    return r;
}
__device__ __forceinline__ u64 bcast2(float a) { return pack2(a, a); }
__device__ __forceinline__ void unpack2(u64 v, float& a, float& b) {
    asm("mov.b64 {%0, %1}, %2;" : "=f"(a), "=f"(b) : "l"(v));
}

#define FMA2(d, a, b, c) asm("fma.rn.f32x2 %0, %1, %2, %3;" : "=l"(d) : "l"(a), "l"(b), "l"(c))
#define MUL2(d, a, b)    asm("mul.rn.f32x2 %0, %1, %2;"     : "=l"(d) : "l"(a), "l"(b))
#define ADD2(d, a, b)    asm("add.rn.f32x2 %0, %1, %2;"     : "=l"(d) : "l"(a), "l"(b))

__global__ __launch_bounds__(128, 4)
void metricnet_kernel(const float* __restrict__ Re_s,
                      const float* __restrict__ Im_s,
                      const float* __restrict__ Omega,
                      const float* __restrict__ PiT,
                      const float* __restrict__ B,
                      float* __restrict__ out)
{
    const float DEL_Z = 0.9f / 512.0f;
    const float MU2   = 1.0f;

    // Per-layer packed (duplicated-lane) coefficient tables; broadcast LDS reads.
    // Record: {P, Q} {C1d(=2*inv1), Ra(=DEL_Z*R)} {Ua(=-DEL_Z*U)}
    __shared__ ulonglong2 tabPQ[TAB_N];
    __shared__ ulonglong2 tabCR[TAB_N];
    __shared__ u64        tabU [TAB_N];

    const int tid = threadIdx.x;
    const float pit = PiT[0];

    for (int l = tid; l < TAB_N; l += blockDim.x) {
        int   lc   = (l < N_LAYERS) ? l : (N_LAYERS - 1);   // pad entry = copy
        float z    = DEL_Z * (float)lc;          // Z_INI = 0
        float omz  = 1.0f - z;
        float inv1 = 1.0f / (pit * omz);
        float inv2 = inv1 / omz;
        float b1   = B[lc];
        float b2   = B[lc + 1];
        float g    = 1.0f - b2 / b1;
        float P    = 1.0f + g;
        float Q    = g * inv1 - DEL_Z * inv2;
        float R    = DEL_Z * (1.0f / (b1 * b1) - inv2 / pit);
        float U    = DEL_Z * z * z * MU2 / b1;
        // Scaled-state (m = DEL_Z*omega*Im) forcing constants:
        //   m_n += DEL_Z*omega*(omega*R - U/omega) = omega^2*(DEL_Z*R) - DEL_Z*U
        float Ra   = DEL_Z * R;
        float Ua   = -DEL_Z * U;
        tabPQ[l] = make_ulonglong2(bcast2(P), bcast2(Q));
        tabCR[l] = make_ulonglong2(bcast2(2.0f * inv1), bcast2(Ra));
        tabU[l]  = bcast2(Ua);
    }
    __syncthreads();

    const int i = blockIdx.x * blockDim.x + tid;   // pair index
    if (i >= NPAIR) return;

    const float2 re0 = ((const float2*)Re_s)[i];
    const float2 im0 = ((const float2*)Im_s)[i];
    const float2 om  = ((const float2*)Omega)[i];

    // Scaled state: m = (DEL_Z*omega) * Im.  Re stays unscaled.
    const float dwx = DEL_Z * om.x, dwy = DEL_Z * om.y;
    u64 Re   = pack2(re0.x, re0.y);
    u64 Mm   = pack2(dwx * im0.x, dwy * im0.y);
    u64 NDW2 = pack2(-dwx * dwx, -dwy * dwy);    // -(DEL_Z*omega)^2
    u64 W2   = pack2(om.x * om.x, om.y * om.y);

    // software prefetch-by-1 through named registers
    ulonglong2 c0 = tabPQ[0];           // P, Q
    ulonglong2 c1 = tabCR[0];           // C1d, Ra
    u64        cu = tabU[0];            // Ua

    #pragma unroll 4
    for (int l = 0; l < N_LAYERS; ++l) {
        ulonglong2 n0 = tabPQ[l + 1];
        ulonglong2 n1 = tabCR[l + 1];
        u64        nu = tabU[l + 1];

        u64 P = c0.x, Q = c0.y, C1d = c1.x, Ra = c1.y, Ua = cu;

        // off-critical-path layer x thread combine
        u64 Cp;
        FMA2(Cp, W2, Ra, Ua);           // omega^2*DEL_Z*R - DEL_Z*U

        // s = m + P ; s2 = P + 2m ; w = m*C1d + Q
        u64 s, s2, w;
        ADD2(s,  Mm, P);
        ADD2(s2, s,  Mm);
        FMA2(w,  Mm, C1d, Q);

        // Re_n = Re*(P + 2m) + (m*C1d + Q)
        u64 Ren;
        FMA2(Ren, Re, s2, w);

        // acc = m*(m + P) + Cp
        u64 acc;
        FMA2(acc, Mm, s, Cp);

        // m_n = acc - DW^2 * Ren*(Ren + C1d)
        u64 tv, t, Mn;
        ADD2(tv, Ren, C1d);
        MUL2(t,  Ren, tv);
        FMA2(Mn, NDW2, t, acc);

        Re = Ren;
        Mm = Mn;

        c0 = n0; c1 = n1; cu = nu;
    }

    float2 reo, mo;
    unpack2(Re, reo.x, reo.y);
    unpack2(Mm, mo.x, mo.y);
    float2 imo;
    imo.x = mo.x / dwx;                 // Im = m / (DEL_Z*omega)
    imo.y = mo.y / dwy;
    ((float2*)out)[i]           = reo;   // Re_f -> out[0 : BATCH)
    ((float2*)(out + BATCH))[i] = imo;   // Im_f -> out[BATCH : 2*BATCH)
}

extern "C" void kernel_launch(void* const* d_in, const int* in_sizes, int n_in,
                              void* d_out, int out_size)
{
    const float* Re_s  = (const float*)d_in[0];
    const float* Im_s  = (const float*)d_in[1];
    const float* Omega = (const float*)d_in[2];
    const float* PiT   = (const float*)d_in[3];
    const float* B     = (const float*)d_in[4];
    float* out = (float*)d_out;

    const int threads = 128;
    const int blocks  = (NPAIR + threads - 1) / threads;   // 512 blocks
    metricnet_kernel<<<blocks, threads>>>(Re_s, Im_s, Omega, PiT, B, out);
}

// round 9
// speedup vs baseline: 1.3457x; 1.0057x over previous
#include <cuda_runtime.h>
#include <cstdint>

#define N_LAYERS 512
#define BATCH    131072
#define NPAIR    (BATCH / 2)          // 65536 float2 pairs
#define HALFPAIR (NPAIR / 2)          // 32768: each thread owns pair i and i+HALFPAIR
#define TAB_N    (N_LAYERS + 1)       // padded for branch-free prefetch

typedef unsigned long long u64;

__device__ __forceinline__ u64 pack2(float a, float b) {
    u64 r;
    asm("mov.b64 %0, {%1, %2};" : "=l"(r) : "f"(a), "f"(b));
    return r;
}
__device__ __forceinline__ u64 bcast2(float a) { return pack2(a, a); }
__device__ __forceinline__ void unpack2(u64 v, float& a, float& b) {
    asm("mov.b64 {%0, %1}, %2;" : "=f"(a), "=f"(b) : "l"(v));
}

#define FMA2(d, a, b, c) asm("fma.rn.f32x2 %0, %1, %2, %3;" : "=l"(d) : "l"(a), "l"(b), "l"(c))
#define MUL2(d, a, b)    asm("mul.rn.f32x2 %0, %1, %2;"     : "=l"(d) : "l"(a), "l"(b))
#define ADD2(d, a, b)    asm("add.rn.f32x2 %0, %1, %2;"     : "=l"(d) : "l"(a), "l"(b))

__global__ __launch_bounds__(128, 2)
void metricnet_kernel(const float* __restrict__ Re_s,
                      const float* __restrict__ Im_s,
                      const float* __restrict__ Omega,
                      const float* __restrict__ PiT,
                      const float* __restrict__ B,
                      float* __restrict__ out)
{
    const float DEL_Z = 0.9f / 512.0f;
    const float MU2   = 1.0f;

    // Per-layer packed (duplicated-lane) coefficient tables; broadcast LDS reads.
    // Record: {P, Q} {C1d(=2*inv1), Ra(=DEL_Z*R)} {Ua(=-DEL_Z*U)}
    __shared__ ulonglong2 tabPQ[TAB_N];
    __shared__ ulonglong2 tabCR[TAB_N];
    __shared__ u64        tabU [TAB_N];

    const int tid = threadIdx.x;
    const float pit = PiT[0];

    for (int l = tid; l < TAB_N; l += blockDim.x) {
        int   lc   = (l < N_LAYERS) ? l : (N_LAYERS - 1);   // pad entry = copy
        float z    = DEL_Z * (float)lc;          // Z_INI = 0
        float omz  = 1.0f - z;
        float inv1 = 1.0f / (pit * omz);
        float inv2 = inv1 / omz;
        float b1   = B[lc];
        float b2   = B[lc + 1];
        float g    = 1.0f - b2 / b1;
        float P    = 1.0f + g;
        float Q    = g * inv1 - DEL_Z * inv2;
        float R    = DEL_Z * (1.0f / (b1 * b1) - inv2 / pit);
        float U    = DEL_Z * z * z * MU2 / b1;
        float Ra   = DEL_Z * R;                  // scaled-state forcing (x DEL_Z)
        float Ua   = -DEL_Z * U;
        tabPQ[l] = make_ulonglong2(bcast2(P), bcast2(Q));
        tabCR[l] = make_ulonglong2(bcast2(2.0f * inv1), bcast2(Ra));
        tabU[l]  = bcast2(Ua);
    }
    __syncthreads();

    // Two chains per thread: pair indices i0 and i0 + HALFPAIR (both coalesced).
    const int i0 = blockIdx.x * blockDim.x + tid;
    const int i1 = i0 + HALFPAIR;

    const float2 reA = ((const float2*)Re_s)[i0];
    const float2 imA = ((const float2*)Im_s)[i0];
    const float2 omA = ((const float2*)Omega)[i0];
    const float2 reB = ((const float2*)Re_s)[i1];
    const float2 imB = ((const float2*)Im_s)[i1];
    const float2 omB = ((const float2*)Omega)[i1];

    // Scaled state: m = (DEL_Z*omega) * Im.  Re stays unscaled.
    const float dwAx = DEL_Z * omA.x, dwAy = DEL_Z * omA.y;
    const float dwBx = DEL_Z * omB.x, dwBy = DEL_Z * omB.y;

    u64 ReA   = pack2(reA.x, reA.y);
    u64 MmA   = pack2(dwAx * imA.x, dwAy * imA.y);
    u64 NDW2A = pack2(-dwAx * dwAx, -dwAy * dwAy);
    u64 W2A   = pack2(omA.x * omA.x, omA.y * omA.y);

    u64 ReB   = pack2(reB.x, reB.y);
    u64 MmB   = pack2(dwBx * imB.x, dwBy * imB.y);
    u64 NDW2B = pack2(-dwBx * dwBx, -dwBy * dwBy);
    u64 W2B   = pack2(omB.x * omB.x, omB.y * omB.y);

    // software prefetch-by-1 through named registers (shared by both chains)
    ulonglong2 c0 = tabPQ[0];           // P, Q
    ulonglong2 c1 = tabCR[0];           // C1d, Ra
    u64        cu = tabU[0];            // Ua

    #pragma unroll 4
    for (int l = 0; l < N_LAYERS; ++l) {
        ulonglong2 n0 = tabPQ[l + 1];
        ulonglong2 n1 = tabCR[l + 1];
        u64        nu = tabU[l + 1];

        u64 P = c0.x, Q = c0.y, C1d = c1.x, Ra = c1.y, Ua = cu;

        // ----- chain A -----
        u64 CpA, sA, s2A, wA, RenA, accA, tvA, tA, MnA;
        FMA2(CpA, W2A, Ra, Ua);
        ADD2(sA,  MmA, P);
        ADD2(s2A, sA,  MmA);
        FMA2(wA,  MmA, C1d, Q);
        FMA2(RenA, ReA, s2A, wA);
        FMA2(accA, MmA, sA, CpA);
        ADD2(tvA, RenA, C1d);
        MUL2(tA,  RenA, tvA);
        FMA2(MnA, NDW2A, tA, accA);

        // ----- chain B -----
        u64 CpB, sB, s2B, wB, RenB, accB, tvB, tB, MnB;
        FMA2(CpB, W2B, Ra, Ua);
        ADD2(sB,  MmB, P);
        ADD2(s2B, sB,  MmB);
        FMA2(wB,  MmB, C1d, Q);
        FMA2(RenB, ReB, s2B, wB);
        FMA2(accB, MmB, sB, CpB);
        ADD2(tvB, RenB, C1d);
        MUL2(tB,  RenB, tvB);
        FMA2(MnB, NDW2B, tB, accB);

        ReA = RenA; MmA = MnA;
        ReB = RenB; MmB = MnB;

        c0 = n0; c1 = n1; cu = nu;
    }

    float2 reoA, moA, reoB, moB;
    unpack2(ReA, reoA.x, reoA.y);
    unpack2(MmA, moA.x, moA.y);
    unpack2(ReB, reoB.x, reoB.y);
    unpack2(MmB, moB.x, moB.y);

    float2 imoA, imoB;
    imoA.x = moA.x / dwAx;  imoA.y = moA.y / dwAy;   // Im = m / (DEL_Z*omega)
    imoB.x = moB.x / dwBx;  imoB.y = moB.y / dwBy;

    ((float2*)out)[i0]           = reoA;   // Re_f -> out[0 : BATCH)
    ((float2*)out)[i1]           = reoB;
    ((float2*)(out + BATCH))[i0] = imoA;   // Im_f -> out[BATCH : 2*BATCH)
    ((float2*)(out + BATCH))[i1] = imoB;
}

extern "C" void kernel_launch(void* const* d_in, const int* in_sizes, int n_in,
                              void* d_out, int out_size)
{
    const float* Re_s  = (const float*)d_in[0];
    const float* Im_s  = (const float*)d_in[1];
    const float* Omega = (const float*)d_in[2];
    const float* PiT   = (const float*)d_in[3];
    const float* B     = (const float*)d_in[4];
    float* out = (float*)d_out;

    const int threads = 128;
    const int blocks  = HALFPAIR / threads;    // 256 blocks, exact
    metricnet_kernel<<<blocks, threads>>>(Re_s, Im_s, Omega, PiT, B, out);
}

// round 10
// speedup vs baseline: 1.3746x; 1.0215x over previous
#include <cuda_runtime.h>
#include <cstdint>

#define N_LAYERS 512
#define BATCH    131072
#define NPAIR    (BATCH / 2)          // 65536 float2 pairs
#define CHAINS   4                    // chains per thread
#define STRIDE   (NPAIR / CHAINS)     // 16384
#define TAB_N    (N_LAYERS + 1)       // padded for branch-free prefetch

typedef unsigned long long u64;

__device__ __forceinline__ u64 pack2(float a, float b) {
    u64 r;
    asm("mov.b64 %0, {%1, %2};" : "=l"(r) : "f"(a), "f"(b));
    return r;
}
__device__ __forceinline__ u64 bcast2(float a) { return pack2(a, a); }
__device__ __forceinline__ void unpack2(u64 v, float& a, float& b) {
    asm("mov.b64 {%0, %1}, %2;" : "=f"(a), "=f"(b) : "l"(v));
}

#define FMA2(d, a, b, c) asm("fma.rn.f32x2 %0, %1, %2, %3;" : "=l"(d) : "l"(a), "l"(b), "l"(c))
#define MUL2(d, a, b)    asm("mul.rn.f32x2 %0, %1, %2;"     : "=l"(d) : "l"(a), "l"(b))
#define ADD2(d, a, b)    asm("add.rn.f32x2 %0, %1, %2;"     : "=l"(d) : "l"(a), "l"(b))

__global__ __launch_bounds__(128, 1)
void metricnet_kernel(const float* __restrict__ Re_s,
                      const float* __restrict__ Im_s,
                      const float* __restrict__ Omega,
                      const float* __restrict__ PiT,
                      const float* __restrict__ B,
                      float* __restrict__ out)
{
    const float DEL_Z = 0.9f / 512.0f;
    const float MU2   = 1.0f;

    // Per-layer packed (duplicated-lane) coefficient tables; broadcast LDS reads.
    // Record: {P, Q} {C1d(=2*inv1), Ra(=DEL_Z*R)} {Ua(=-DEL_Z*U)}
    __shared__ ulonglong2 tabPQ[TAB_N];
    __shared__ ulonglong2 tabCR[TAB_N];
    __shared__ u64        tabU [TAB_N];

    const int tid = threadIdx.x;
    const float pit = PiT[0];

    for (int l = tid; l < TAB_N; l += blockDim.x) {
        int   lc   = (l < N_LAYERS) ? l : (N_LAYERS - 1);   // pad entry = copy
        float z    = DEL_Z * (float)lc;          // Z_INI = 0
        float omz  = 1.0f - z;
        float inv1 = 1.0f / (pit * omz);
        float inv2 = inv1 / omz;
        float b1   = B[lc];
        float b2   = B[lc + 1];
        float g    = 1.0f - b2 / b1;
        float P    = 1.0f + g;
        float Q    = g * inv1 - DEL_Z * inv2;
        float R    = DEL_Z * (1.0f / (b1 * b1) - inv2 / pit);
        float U    = DEL_Z * z * z * MU2 / b1;
        float Ra   = DEL_Z * R;                  // scaled-state forcing (x DEL_Z)
        float Ua   = -DEL_Z * U;
        tabPQ[l] = make_ulonglong2(bcast2(P), bcast2(Q));
        tabCR[l] = make_ulonglong2(bcast2(2.0f * inv1), bcast2(Ra));
        tabU[l]  = bcast2(Ua);
    }
    __syncthreads();

    // Four chains per thread at stride STRIDE (all loads coalesced).
    const int i0 = blockIdx.x * blockDim.x + tid;   // [0, 16384)

    u64 Re[CHAINS], Mm[CHAINS], NDW2[CHAINS], W2[CHAINS];
    float dwx[CHAINS], dwy[CHAINS];

    #pragma unroll
    for (int k = 0; k < CHAINS; ++k) {
        const int idx = i0 + k * STRIDE;
        const float2 re = ((const float2*)Re_s)[idx];
        const float2 im = ((const float2*)Im_s)[idx];
        const float2 om = ((const float2*)Omega)[idx];
        dwx[k] = DEL_Z * om.x;
        dwy[k] = DEL_Z * om.y;
        Re[k]   = pack2(re.x, re.y);
        Mm[k]   = pack2(dwx[k] * im.x, dwy[k] * im.y);     // m = DEL_Z*omega*Im
        NDW2[k] = pack2(-dwx[k] * dwx[k], -dwy[k] * dwy[k]);
        W2[k]   = pack2(om.x * om.x, om.y * om.y);
    }

    // software prefetch-by-1 through named registers (shared by all chains)
    ulonglong2 c0 = tabPQ[0];           // P, Q
    ulonglong2 c1 = tabCR[0];           // C1d, Ra
    u64        cu = tabU[0];            // Ua

    #pragma unroll 4
    for (int l = 0; l < N_LAYERS; ++l) {
        ulonglong2 n0 = tabPQ[l + 1];
        ulonglong2 n1 = tabCR[l + 1];
        u64        nu = tabU[l + 1];

        u64 P = c0.x, Q = c0.y, C1d = c1.x, Ra = c1.y, Ua = cu;

        #pragma unroll
        for (int k = 0; k < CHAINS; ++k) {
            u64 Cp, s, s2, w, Ren, acc, tv, t, Mn;
            FMA2(Cp, W2[k], Ra, Ua);        // omega^2*DEL_Z*R - DEL_Z*U
            ADD2(s,  Mm[k], P);
            ADD2(s2, s,  Mm[k]);
            FMA2(w,  Mm[k], C1d, Q);
            FMA2(Ren, Re[k], s2, w);        // Re_n = Re*(P+2m) + (m*C1d + Q)
            FMA2(acc, Mm[k], s, Cp);        // m*(m+P) + Cp
            ADD2(tv, Ren, C1d);
            MUL2(t,  Ren, tv);
            FMA2(Mn, NDW2[k], t, acc);      // m_n = acc - DW^2*Ren*(Ren+C1d)
            Re[k] = Ren;
            Mm[k] = Mn;
        }

        c0 = n0; c1 = n1; cu = nu;
    }

    #pragma unroll
    for (int k = 0; k < CHAINS; ++k) {
        const int idx = i0 + k * STRIDE;
        float2 reo, mo, imo;
        unpack2(Re[k], reo.x, reo.y);
        unpack2(Mm[k], mo.x, mo.y);
        imo.x = mo.x / dwx[k];              // Im = m / (DEL_Z*omega)
        imo.y = mo.y / dwy[k];
        ((float2*)out)[idx]           = reo;   // Re_f -> out[0 : BATCH)
        ((float2*)(out + BATCH))[idx] = imo;   // Im_f -> out[BATCH : 2*BATCH)
    }
}

extern "C" void kernel_launch(void* const* d_in, const int* in_sizes, int n_in,
                              void* d_out, int out_size)
{
    const float* Re_s  = (const float*)d_in[0];
    const float* Im_s  = (const float*)d_in[1];
    const float* Omega = (const float*)d_in[2];
    const float* PiT   = (const float*)d_in[3];
    const float* B     = (const float*)d_in[4];
    float* out = (float*)d_out;

    const int threads = 128;
    const int blocks  = STRIDE / threads;      // 128 blocks, exact; <=1 CTA/SM
    metricnet_kernel<<<blocks, threads>>>(Re_s, Im_s, Omega, PiT, B, out);
}

// round 11
// speedup vs baseline: 1.5265x; 1.1105x over previous
#include <cuda_runtime.h>
#include <cstdint>

#define N_LAYERS 512
#define BATCH    131072
#define NPAIR    (BATCH / 2)          // 65536 float2 pairs
#define CHAINS   4                    // chains per thread
#define STRIDE   (NPAIR / CHAINS)     // 16384
#define TAB_N    (N_LAYERS + 1)       // padded for branch-free prefetch

typedef unsigned long long u64;

__device__ __forceinline__ u64 pack2(float a, float b) {
    u64 r;
    asm("mov.b64 %0, {%1, %2};" : "=l"(r) : "f"(a), "f"(b));
    return r;
}
__device__ __forceinline__ u64 bcast2(float a) { return pack2(a, a); }
__device__ __forceinline__ void unpack2(u64 v, float& a, float& b) {
    asm("mov.b64 {%0, %1}, %2;" : "=f"(a), "=f"(b) : "l"(v));
}

#define FMA2(d, a, b, c) asm("fma.rn.f32x2 %0, %1, %2, %3;" : "=l"(d) : "l"(a), "l"(b), "l"(c))
#define MUL2(d, a, b)    asm("mul.rn.f32x2 %0, %1, %2;"     : "=l"(d) : "l"(a), "l"(b))
#define ADD2(d, a, b)    asm("add.rn.f32x2 %0, %1, %2;"     : "=l"(d) : "l"(a), "l"(b))

__device__ __forceinline__ float inv1_of(int l, float pit) {
    const float DEL_Z = 0.9f / 512.0f;
    return 1.0f / (pit * (1.0f - DEL_Z * (float)l));
}

__global__ __launch_bounds__(128, 1)
void metricnet_kernel(const float* __restrict__ Re_s,
                      const float* __restrict__ Im_s,
                      const float* __restrict__ Omega,
                      const float* __restrict__ PiT,
                      const float* __restrict__ B,
                      float* __restrict__ out)
{
    const float DEL_Z = 0.9f / 512.0f;
    const float MU2   = 1.0f;

    // Per-layer packed (duplicated-lane) coefficient tables; broadcast LDS reads.
    // State: X = Re + inv1_l,  m = DEL_Z*omega*Im.
    // Record: {P, Q2} {D2(=2*delta), Ra2} {Ua}
    __shared__ ulonglong2 tabPQ[TAB_N];
    __shared__ ulonglong2 tabDR[TAB_N];
    __shared__ u64        tabU [TAB_N];

    const int tid = threadIdx.x;
    const float pit = PiT[0];

    for (int l = tid; l < TAB_N; l += blockDim.x) {
        int   lc    = (l < N_LAYERS) ? l : (N_LAYERS - 1);   // pad entry (content unused)
        float z     = DEL_Z * (float)lc;          // Z_INI = 0
        float omz   = 1.0f - z;
        float inv1  = 1.0f / (pit * omz);
        float inv1n = inv1_of(lc + 1, pit);       // next layer's inv1
        float inv2  = inv1 / omz;
        float b1    = B[lc];
        float b2    = B[lc + 1];
        float g     = 1.0f - b2 / b1;
        float P     = 1.0f + g;
        float Q     = g * inv1 - DEL_Z * inv2;
        float R     = DEL_Z * (1.0f / (b1 * b1) - inv2 / pit);
        float U     = DEL_Z * z * z * MU2 / b1;
        float delta = inv1 - inv1n;
        // X' = X*(P+2m) + Q2 ;  Q2 = Q - P*inv1 + inv1_next
        float Q2    = Q - P * inv1 + inv1n;
        // m' = m*(m+P) + W2*Ra2 + Ua - dw^2 * X'*(X'+2*delta)
        //   Ra2 = DEL_Z*R + DEL_Z^2*(inv1^2 - delta^2)
        float Ra2   = DEL_Z * R + (DEL_Z * DEL_Z) * (inv1 * inv1 - delta * delta);
        float Ua    = -DEL_Z * U;
        tabPQ[l] = make_ulonglong2(bcast2(P), bcast2(Q2));
        tabDR[l] = make_ulonglong2(bcast2(2.0f * delta), bcast2(Ra2));
        tabU[l]  = bcast2(Ua);
    }
    __syncthreads();

    // Four chains per thread at stride STRIDE (all loads coalesced).
    const int i0 = blockIdx.x * blockDim.x + tid;   // [0, 16384)

    const float inv1_0   = 1.0f / pit;                        // inv1 at l=0
    const float inv1_end = inv1_of(N_LAYERS, pit);            // inv1 at l=512

    u64 X[CHAINS], Mm[CHAINS], NDW2[CHAINS], W2[CHAINS];
    float dwx[CHAINS], dwy[CHAINS];

    #pragma unroll
    for (int k = 0; k < CHAINS; ++k) {
        const int idx = i0 + k * STRIDE;
        const float2 re = ((const float2*)Re_s)[idx];
        const float2 im = ((const float2*)Im_s)[idx];
        const float2 om = ((const float2*)Omega)[idx];
        dwx[k] = DEL_Z * om.x;
        dwy[k] = DEL_Z * om.y;
        X[k]    = pack2(re.x + inv1_0, re.y + inv1_0);        // X = Re + inv1_0
        Mm[k]   = pack2(dwx[k] * im.x, dwy[k] * im.y);        // m = DEL_Z*omega*Im
        NDW2[k] = pack2(-dwx[k] * dwx[k], -dwy[k] * dwy[k]);
        W2[k]   = pack2(om.x * om.x, om.y * om.y);
    }

    // software prefetch-by-1 through named registers (shared by all chains)
    ulonglong2 c0 = tabPQ[0];           // P, Q2
    ulonglong2 c1 = tabDR[0];           // D2, Ra2
    u64        cu = tabU[0];            // Ua

    #pragma unroll 4
    for (int l = 0; l < N_LAYERS; ++l) {
        ulonglong2 n0 = tabPQ[l + 1];
        ulonglong2 n1 = tabDR[l + 1];
        u64        nu = tabU[l + 1];

        u64 P = c0.x, Q2 = c0.y, D2 = c1.x, Ra2 = c1.y, Ua = cu;

        #pragma unroll
        for (int k = 0; k < CHAINS; ++k) {
            u64 Cp, s, s2, Xn, acc, tv, t, Mn;
            FMA2(Cp, W2[k], Ra2, Ua);       // forcing + quad correction
            ADD2(s,  Mm[k], P);
            ADD2(s2, s,  Mm[k]);            // P + 2m
            FMA2(Xn, X[k], s2, Q2);         // X' = X*(P+2m) + Q2
            FMA2(acc, Mm[k], s, Cp);        // m*(m+P) + Cp
            ADD2(tv, Xn, D2);               // X' + 2*delta
            MUL2(t,  Xn, tv);
            FMA2(Mn, NDW2[k], t, acc);      // m' = acc - dw^2 * X'*(X'+2delta)
            X[k]  = Xn;
            Mm[k] = Mn;
        }

        c0 = n0; c1 = n1; cu = nu;
    }

    #pragma unroll
    for (int k = 0; k < CHAINS; ++k) {
        const int idx = i0 + k * STRIDE;
        float2 xo, mo, reo, imo;
        unpack2(X[k],  xo.x, xo.y);
        unpack2(Mm[k], mo.x, mo.y);
        reo.x = xo.x - inv1_end;            // Re = X - inv1_512
        reo.y = xo.y - inv1_end;
        imo.x = mo.x / dwx[k];              // Im = m / (DEL_Z*omega)
        imo.y = mo.y / dwy[k];
        ((float2*)out)[idx]           = reo;   // Re_f -> out[0 : BATCH)
        ((float2*)(out + BATCH))[idx] = imo;   // Im_f -> out[BATCH : 2*BATCH)
    }
}

extern "C" void kernel_launch(void* const* d_in, const int* in_sizes, int n_in,
                              void* d_out, int out_size)
{
    const float* Re_s  = (const float*)d_in[0];
    const float* Im_s  = (const float*)d_in[1];
    const float* Omega = (const float*)d_in[2];
    const float* PiT   = (const float*)d_in[3];
    const float* B     = (const float*)d_in[4];
    float* out = (float*)d_out;

    const int threads = 128;
    const int blocks  = STRIDE / threads;      // 128 blocks, exact; <=1 CTA/SM
    metricnet_kernel<<<blocks, threads>>>(Re_s, Im_s, Omega, PiT, B, out);
}

// round 13
// speedup vs baseline: 1.6384x; 1.0733x over previous
#include <cuda_runtime.h>
#include <cstdint>

#define N_LAYERS 512
#define BATCH    131072
#define NPAIR    (BATCH / 2)          // 65536 float2 pairs
#define CHAINS   4                    // chains per thread
#define STRIDE   (NPAIR / CHAINS)     // 16384
#define TAB_N    (N_LAYERS + 1)       // padded for branch-free prefetch

typedef unsigned long long u64;

__device__ __forceinline__ u64 pack2(float a, float b) {
    u64 r;
    asm("mov.b64 %0, {%1, %2};" : "=l"(r) : "f"(a), "f"(b));
    return r;
}
__device__ __forceinline__ u64 bcast2(float a) { return pack2(a, a); }
__device__ __forceinline__ void unpack2(u64 v, float& a, float& b) {
    asm("mov.b64 {%0, %1}, %2;" : "=f"(a), "=f"(b) : "l"(v));
}

#define FMA2(d, a, b, c) asm("fma.rn.f32x2 %0, %1, %2, %3;" : "=l"(d) : "l"(a), "l"(b), "l"(c))
#define MUL2(d, a, b)    asm("mul.rn.f32x2 %0, %1, %2;"     : "=l"(d) : "l"(a), "l"(b))
#define ADD2(d, a, b)    asm("add.rn.f32x2 %0, %1, %2;"     : "=l"(d) : "l"(a), "l"(b))

__device__ __forceinline__ float inv1_of(int l, float pit) {
    const float DEL_Z = 0.9f / 512.0f;
    return 1.0f / (pit * (1.0f - DEL_Z * (float)l));
}

__global__ __launch_bounds__(128, 1)
void metricnet_kernel(const float* __restrict__ Re_s,
                      const float* __restrict__ Im_s,
                      const float* __restrict__ Omega,
                      const float* __restrict__ PiT,
                      const float* __restrict__ B,
                      float* __restrict__ out)
{
    const float DEL_Z = 0.9f / 512.0f;
    const float MU2   = 1.0f;

    // States (all natural magnitude, no shift):
    //   Xd = DEL_Z * (Re + inv1_l),   m = DEL_Z*omega*Im.
    // Update:
    //   Xd' = Xd*(P+2m) + Q2d
    //   m'  = m*(m+P) + Ua + omega^2 * ( Ra2 - Xd'*(Xd' + D2d) )
    // Tables: {P, Q2d} {ND2d(=-D2d), Ra2} {Ua}
    __shared__ ulonglong2 tabPQ[TAB_N];
    __shared__ ulonglong2 tabDR[TAB_N];
    __shared__ u64        tabU [TAB_N];

    const int tid = threadIdx.x;
    const float pit = PiT[0];

    for (int l = tid; l < TAB_N; l += blockDim.x) {
        int   lc    = (l < N_LAYERS) ? l : (N_LAYERS - 1);   // pad entry (content unused)
        float z     = DEL_Z * (float)lc;          // Z_INI = 0
        float omz   = 1.0f - z;
        float inv1  = 1.0f / (pit * omz);
        float inv1n = inv1_of(lc + 1, pit);
        float inv2  = inv1 / omz;
        float b1    = B[lc];
        float b2    = B[lc + 1];
        float g     = 1.0f - b2 / b1;
        float P     = 1.0f + g;
        float Q     = g * inv1 - DEL_Z * inv2;
        float R     = DEL_Z * (1.0f / (b1 * b1) - inv2 / pit);
        float U     = DEL_Z * z * z * MU2 / b1;
        float delta = inv1 - inv1n;
        float Q2    = Q - P * inv1 + inv1n;
        // Same Ra2/Ua as the passing R11 kernel:
        float Ra2   = DEL_Z * R + (DEL_Z * DEL_Z) * (inv1 * inv1 - delta * delta);
        float Ua    = -DEL_Z * U;
        // X-state scaled by DEL_Z (global):
        float Q2d   = DEL_Z * Q2;
        float ND2d  = -2.0f * DEL_Z * delta;
        tabPQ[l] = make_ulonglong2(bcast2(P),    bcast2(Q2d));
        tabDR[l] = make_ulonglong2(bcast2(ND2d), bcast2(Ra2));
        tabU[l]  = bcast2(Ua);
    }
    __syncthreads();

    // Four chains per thread at stride STRIDE (all loads coalesced).
    const int i0 = blockIdx.x * blockDim.x + tid;   // [0, 16384)

    const float inv1_0   = 1.0f / pit;                 // inv1 at l=0
    const float inv1_end = inv1_of(N_LAYERS, pit);     // inv1 at l=512

    u64 Xd[CHAINS], Mm[CHAINS], W2[CHAINS];
    float dwx[CHAINS], dwy[CHAINS];

    #pragma unroll
    for (int k = 0; k < CHAINS; ++k) {
        const int idx = i0 + k * STRIDE;
        const float2 re = ((const float2*)Re_s)[idx];
        const float2 im = ((const float2*)Im_s)[idx];
        const float2 om = ((const float2*)Omega)[idx];
        dwx[k] = DEL_Z * om.x;
        dwy[k] = DEL_Z * om.y;
        Xd[k] = pack2(DEL_Z * (re.x + inv1_0), DEL_Z * (re.y + inv1_0));
        Mm[k] = pack2(dwx[k] * im.x, dwy[k] * im.y);       // m = DEL_Z*omega*Im
        W2[k] = pack2(om.x * om.x, om.y * om.y);
    }

    const u64 NONE = bcast2(-1.0f);

    // software prefetch-by-1 through named registers (shared by all chains)
    ulonglong2 c0 = tabPQ[0];           // P, Q2d
    ulonglong2 c1 = tabDR[0];           // ND2d, Ra2
    u64        cu = tabU[0];            // Ua

    #pragma unroll 4
    for (int l = 0; l < N_LAYERS; ++l) {
        ulonglong2 n0 = tabPQ[l + 1];
        ulonglong2 n1 = tabDR[l + 1];
        u64        nu = tabU[l + 1];

        u64 P = c0.x, Q2d = c0.y, ND2d = c1.x, Ra2 = c1.y, Ua = cu;

        #pragma unroll
        for (int k = 0; k < CHAINS; ++k) {
            u64 s, s2, Xn, acc, tv, u, Mn;
            ADD2(s,  Mm[k], P);             // m + P
            ADD2(s2, s,  Mm[k]);            // P + 2m
            FMA2(Xn, Xd[k], s2, Q2d);       // Xd' = Xd*(P+2m) + Q2d
            FMA2(acc, Mm[k], s, Ua);        // m*(m+P) + Ua
            FMA2(tv, NONE, Xn, ND2d);       // -Xd' - D2d
            FMA2(u,  Xn, tv, Ra2);          // Ra2 - Xd'*(Xd'+D2d)
            FMA2(Mn, W2[k], u, acc);        // m' = acc + omega^2 * u
            Xd[k] = Xn;
            Mm[k] = Mn;
        }

        c0 = n0; c1 = n1; cu = nu;
    }

    #pragma unroll
    for (int k = 0; k < CHAINS; ++k) {
        const int idx = i0 + k * STRIDE;
        float2 xo, mo, reo, imo;
        unpack2(Xd[k], xo.x, xo.y);
        unpack2(Mm[k], mo.x, mo.y);
        reo.x = xo.x / DEL_Z - inv1_end;    // Re = Xd/DEL_Z - inv1_512
        reo.y = xo.y / DEL_Z - inv1_end;
        imo.x = mo.x / dwx[k];              // Im = m / (DEL_Z*omega)
        imo.y = mo.y / dwy[k];
        ((float2*)out)[idx]           = reo;   // Re_f -> out[0 : BATCH)
        ((float2*)(out + BATCH))[idx] = imo;   // Im_f -> out[BATCH : 2*BATCH)
    }
}

extern "C" void kernel_launch(void* const* d_in, const int* in_sizes, int n_in,
                              void* d_out, int out_size)
{
    const float* Re_s  = (const float*)d_in[0];
    const float* Im_s  = (const float*)d_in[1];
    const float* Omega = (const float*)d_in[2];
    const float* PiT   = (const float*)d_in[3];
    const float* B     = (const float*)d_in[4];
    float* out = (float*)d_out;

    const int threads = 128;
    const int blocks  = STRIDE / threads;      // 128 blocks, 1 CTA/SM
    metricnet_kernel<<<blocks, threads>>>(Re_s, Im_s, Omega, PiT, B, out);
}